// round 1
// baseline (speedup 1.0000x reference)
#include <cuda_runtime.h>
#include <cuda_bf16.h>
#include <cstdint>

// ---------------- geometry constants (match reference) ----------------
#define VOL      256
#define N_PROJ   256
#define N_DET    384
#define N_SAMP   256
#define SID_F    400.0f
#define SDD_F    800.0f
#define DETSP    1.2f

// theta step = 2*pi/256 (fp32 of the double value)
#define TH_STEP  0.024543692442321777f
// dt = 256*sqrt(2)/256 = sqrt(2), fp32
#define DT_F     1.4142135623730951f
// t base = SID - diag/2  (double-folded, then fp32): 400 - 181.01933598375618
#define T_BASE   218.98066401624382f

// Padded quad image: rows 0..256 (y0 = -1..255), cols 0..256 (x0 = -1..255)
// Row stride padded to 264 cells (264*16 = 4224 B = 33 cache lines, line-aligned rows)
#define QROWS    257
#define QCOLS    257
#define QSTRIDE  264
#define QPERB    (QROWS * QSTRIDE)

// 2 batches * 257 * 264 * 16B = ~2.17 MB static scratch (no runtime allocation)
__device__ float4 g_quad[2 * QPERB];

// ---------------------------------------------------------------------
// Prep: build zero-padded 2x2 quad image.
// cell (iy, ix) corresponds to y0 = iy-1, x0 = ix-1 and holds
// { img[y0,x0], img[y0,x0+1], img[y0+1,x0], img[y0+1,x0+1] } with zeros OOB.
// ---------------------------------------------------------------------
__global__ void fanproj_prep_kernel(const float* __restrict__ img)
{
    int idx = blockIdx.x * blockDim.x + threadIdx.x;
    const int total = 2 * QROWS * QCOLS;
    if (idx >= total) return;

    int b  = idx / (QROWS * QCOLS);
    int r  = idx - b * (QROWS * QCOLS);
    int iy = r / QCOLS;
    int ix = r - iy * QCOLS;
    int y0 = iy - 1;
    int x0 = ix - 1;

    const float* im = img + b * (VOL * VOL);

    float v00 = 0.f, v01 = 0.f, v10 = 0.f, v11 = 0.f;
    bool xa = (x0 >= 0)     && (x0 < VOL);
    bool xb = (x0 + 1 >= 0) && (x0 + 1 < VOL);
    if (y0 >= 0 && y0 < VOL) {
        const float* row = im + y0 * VOL;
        if (xa) v00 = row[x0];
        if (xb) v01 = row[x0 + 1];
    }
    if (y0 + 1 >= 0 && y0 + 1 < VOL) {
        const float* row = im + (y0 + 1) * VOL;
        if (xa) v10 = row[x0];
        if (xb) v11 = row[x0 + 1];
    }
    g_quad[b * QPERB + iy * QSTRIDE + ix] = make_float4(v00, v01, v10, v11);
}

// ---------------------------------------------------------------------
// Main: one thread per (batch, angle, detector). 256 samples along ray,
// each sample = one aligned float4 load + a handful of FMAs.
// ---------------------------------------------------------------------
__global__ void __launch_bounds__(128) fanproj_main_kernel(float* __restrict__ out)
{
    int d = blockIdx.x * blockDim.x + threadIdx.x;   // detector 0..383
    int p = blockIdx.y;                              // angle    0..255
    int b = blockIdx.z;                              // batch    0..1
    if (d >= N_DET) return;

    // geometry (once per thread; amortized over 256 samples)
    float theta = (float)p * TH_STEP;
    float sn, cs;
    sincosf(theta, &sn, &cs);

    float off = ((float)d - (float)(N_DET - 1) * 0.5f) * DETSP;

    // ray = SDD*cen + off*u,  cen=(cs,sn), u=(-sn,cs)
    float rx = SDD_F * cs - off * sn;
    float ry = SDD_F * sn + off * cs;
    float inv = rsqrtf(SDD_F * SDD_F + off * off);
    rx *= inv;
    ry *= inv;

    // src = -SID*cen; pixel coords = world + 127.5
    float cx = fmaf(-SID_F, cs, 127.5f);
    float cy = fmaf(-SID_F, sn, 127.5f);

    const float4* __restrict__ quad = g_quad + b * QPERB;

    float acc = 0.f;
    float fs = 0.5f;                                 // (s + 0.5), exact fp32 increments

    #pragma unroll 4
    for (int ss = 0; ss < N_SAMP; ++ss) {
        float t  = fmaf(fs, DT_F, T_BASE);
        fs += 1.0f;
        float fx = fmaf(t, rx, cx);
        float fy = fmaf(t, ry, cy);
        float flx = floorf(fx);
        float fly = floorf(fy);
        float wx = fx - flx;
        float wy = fy - fly;
        int ix = (int)flx + 1;                       // shift into padded grid
        int iy = (int)fly + 1;
        if ((unsigned)ix <= (unsigned)(QCOLS - 1) &&
            (unsigned)iy <= (unsigned)(QROWS - 1)) {
            float4 q = __ldg(quad + iy * QSTRIDE + ix);
            float v0 = fmaf(wx, q.y - q.x, q.x);     // top row lerp
            float v1 = fmaf(wx, q.w - q.z, q.z);     // bottom row lerp
            acc += fmaf(wy, v1 - v0, v0);
        }
    }

    out[(b * N_PROJ + p) * N_DET + d] = acc * DT_F;
}

// ---------------------------------------------------------------------
extern "C" void kernel_launch(void* const* d_in, const int* in_sizes, int n_in,
                              void* d_out, int out_size)
{
    const float* x = (const float*)d_in[0];
    float* out = (float*)d_out;

    const int prep_total = 2 * QROWS * QCOLS;
    fanproj_prep_kernel<<<(prep_total + 255) / 256, 256>>>(x);

    dim3 grid((N_DET + 127) / 128, N_PROJ, 2);
    fanproj_main_kernel<<<grid, 128>>>(out);
}

// round 2
// speedup vs baseline: 1.0842x; 1.0842x over previous
#include <cuda_runtime.h>
#include <cuda_bf16.h>
#include <cstdint>

// ---------------- geometry constants (match reference) ----------------
#define VOL      256
#define N_PROJ   256
#define N_DET    384
#define N_SAMP   256
#define SID_F    400.0f
#define SDD_F    800.0f
#define DETSP    1.2f

#define TH_STEP  0.024543692442321777f   // 2*pi/256 in fp32
#define DT_F     1.4142135623730951f     // diag/N = sqrt(2)
#define T_BASE   218.98066401624382f     // SID - diag/2

// Padded quad grid: index i <-> corner coord c0 = i - 2, covering c0 in [-2, 256].
// i=0 (c0=-2) and i=258 (c0=256) are ALL-ZERO cells (both taps outside image),
// so clamping OOB samples into them contributes exactly 0.
#define QN       259
#define QSTRIDE  264                     // row = 264*16B = 4224B (line-aligned)
#define QPERB    (QN * QSTRIDE)

// Two layouts, 2 batches each: ~4.4 MB static scratch (no runtime allocation).
// A: row-major (maj=y, min=x), cell {v00, v01, v10, v11}
// B: transposed (maj=x, min=y), cell {v00, v10, v01, v11}
__device__ float4 g_quadA[2 * QPERB];
__device__ float4 g_quadB[2 * QPERB];

// ---------------------------------------------------------------------
__global__ void fanproj_prep_kernel(const float* __restrict__ img)
{
    int idx = blockIdx.x * blockDim.x + threadIdx.x;
    const int total = 2 * QN * QN;
    if (idx >= total) return;

    int b  = idx / (QN * QN);
    int r  = idx - b * (QN * QN);
    int iy = r / QN;
    int ix = r - iy * QN;
    int y0 = iy - 2;
    int x0 = ix - 2;

    const float* im = img + b * (VOL * VOL);

    float v00 = 0.f, v01 = 0.f, v10 = 0.f, v11 = 0.f;
    bool xa = (x0 >= 0)     && (x0 < VOL);
    bool xb = (x0 + 1 >= 0) && (x0 + 1 < VOL);
    if (y0 >= 0 && y0 < VOL) {
        const float* row = im + y0 * VOL;
        if (xa) v00 = row[x0];
        if (xb) v01 = row[x0 + 1];
    }
    if (y0 + 1 >= 0 && y0 + 1 < VOL) {
        const float* row = im + (y0 + 1) * VOL;
        if (xa) v10 = row[x0];
        if (xb) v11 = row[x0 + 1];
    }
    g_quadA[b * QPERB + iy * QSTRIDE + ix] = make_float4(v00, v01, v10, v11);
    g_quadB[b * QPERB + ix * QSTRIDE + iy] = make_float4(v00, v10, v01, v11);
}

// ---------------------------------------------------------------------
// One thread per (batch, angle, detector); 256 samples along the ray.
// Layout chosen per angle so the across-warp-varying coordinate is contiguous.
// ---------------------------------------------------------------------
__global__ void __launch_bounds__(128) fanproj_main_kernel(float* __restrict__ out)
{
    int d = blockIdx.x * blockDim.x + threadIdx.x;   // detector 0..383
    int p = blockIdx.y;                              // angle    0..255
    int b = blockIdx.z;                              // batch    0..1
    if (d >= N_DET) return;

    float theta = (float)p * TH_STEP;
    float sn, cs;
    sincosf(theta, &sn, &cs);

    float off = ((float)d - (float)(N_DET - 1) * 0.5f) * DETSP;

    // unit ray dir: (SDD*cs - off*sn, SDD*sn + off*cs) / |.|
    float rx = SDD_F * cs - off * sn;
    float ry = SDD_F * sn + off * cs;
    float inv = rsqrtf(SDD_F * SDD_F + off * off);
    rx *= inv;
    ry *= inv;

    // padded-grid coords: pixel + 127.5, then +2 for the zero-ring shift
    float cx = fmaf(-SID_F, cs, 129.5f);
    float cy = fmaf(-SID_F, sn, 129.5f);

    // detector axis u = (-sn, cs); warp varies along u.
    // |sn| >= |cs|  -> threads vary mostly in x -> want x contiguous -> layout A
    bool useA = fabsf(sn) >= fabsf(cs);

    float rMin = useA ? rx : ry;
    float rMaj = useA ? ry : rx;
    float cMin = useA ? cx : cy;
    float cMaj = useA ? cy : cx;
    const float4* __restrict__ quad = (useA ? g_quadA : g_quadB) + b * QPERB;

    // f(s) = fma(fs, r*dt, base) with base = T_BASE*r + c   (exact fold of
    // f = fma(t, r, c), t = fma(fs, dt, T_BASE) up to fp32 rounding)
    float drMin = rMin * DT_F;
    float drMaj = rMaj * DT_F;
    float bMin  = fmaf(T_BASE, rMin, cMin);
    float bMaj  = fmaf(T_BASE, rMaj, cMaj);

    float acc = 0.f;
    float fs  = 0.5f;

    #pragma unroll 4
    for (int ss = 0; ss < N_SAMP; ++ss) {
        float fM = fmaf(fs, drMaj, bMaj);
        float fm = fmaf(fs, drMin, bMin);
        fs += 1.0f;
        float flM = floorf(fM);
        float flm = floorf(fm);
        float wM = fM - flM;
        float wm = fm - flm;
        int iM = (int)flM;
        int im = (int)flm;
        iM = max(0, min(iM, QN - 1));    // clamped cells are all-zero -> +0
        im = max(0, min(im, QN - 1));
        float4 q = __ldg(quad + iM * QSTRIDE + im);
        float v0 = fmaf(wm, q.y - q.x, q.x);
        float v1 = fmaf(wm, q.w - q.z, q.z);
        acc += fmaf(wM, v1 - v0, v0);
    }

    out[(b * N_PROJ + p) * N_DET + d] = acc * DT_F;
}

// ---------------------------------------------------------------------
extern "C" void kernel_launch(void* const* d_in, const int* in_sizes, int n_in,
                              void* d_out, int out_size)
{
    const float* x = (const float*)d_in[0];
    float* out = (float*)d_out;

    const int prep_total = 2 * QN * QN;
    fanproj_prep_kernel<<<(prep_total + 255) / 256, 256>>>(x);

    dim3 grid((N_DET + 127) / 128, N_PROJ, 2);
    fanproj_main_kernel<<<grid, 128>>>(out);
}

// round 3
// speedup vs baseline: 1.4200x; 1.3097x over previous
#include <cuda_runtime.h>
#include <cuda_fp16.h>
#include <cstdint>

// ---------------- geometry constants (match reference) ----------------
#define VOL      256
#define N_PROJ   256
#define N_DET    384
#define N_SAMP   256
#define SID_F    400.0f
#define SDD_F    800.0f
#define DETSP    1.2f

#define TH_STEP  0.024543692442321777f   // 2*pi/256 in fp32
#define DT_F     1.4142135623730951f     // diag/N = sqrt(2)
#define INV_DT   0.7071067811865476f
#define T_BASE   218.98066401624382f     // SID - diag/2
#define T_END    581.0193359837562f      // SID + diag/2

// Padded fp16 quad grid: cell i <-> corner coord c0 = i - 4, c0 in [-4, 259].
// Cells with c0 <= -2 or c0 >= 256 are all-zero (both taps outside image),
// absorbing the <=2.83px interval-clipping slack without per-sample clamps.
#define QN       264
#define QSTRIDE  264
#define QPAD     4
#define QPERB    (QN * QSTRIDE)

// Two layouts x 2 batches x 264x264 x 8B  =  ~2.23 MB static scratch.
// Cell = uint2: .x = half2{v(M0,m0), v(M1,m0)}, .y = half2{v(M0,m1), v(M1,m1)}
// Layout A: maj = y, min = x.   Layout B: maj = x, min = y.
__device__ uint2 g_qA[2 * QPERB];
__device__ uint2 g_qB[2 * QPERB];

// ---------------------------------------------------------------------
__global__ void fanproj_prep_kernel(const float* __restrict__ img)
{
    int idx = blockIdx.x * blockDim.x + threadIdx.x;
    const int total = 2 * QN * QN;
    if (idx >= total) return;

    int b  = idx / (QN * QN);
    int r  = idx - b * (QN * QN);
    int iy = r / QN;
    int ix = r - iy * QN;
    int y0 = iy - QPAD;
    int x0 = ix - QPAD;

    const float* im = img + b * (VOL * VOL);

    float v00 = 0.f, v01 = 0.f, v10 = 0.f, v11 = 0.f;
    bool xa = (x0 >= 0)     && (x0 < VOL);
    bool xb = (x0 + 1 >= 0) && (x0 + 1 < VOL);
    if (y0 >= 0 && y0 < VOL) {
        const float* row = im + y0 * VOL;
        if (xa) v00 = row[x0];
        if (xb) v01 = row[x0 + 1];
    }
    if (y0 + 1 >= 0 && y0 + 1 < VOL) {
        const float* row = im + (y0 + 1) * VOL;
        if (xa) v10 = row[x0];
        if (xb) v11 = row[x0 + 1];
    }

    __half h00 = __float2half_rn(v00);
    __half h01 = __float2half_rn(v01);
    __half h10 = __float2half_rn(v10);
    __half h11 = __float2half_rn(v11);

    // Layout A (maj=y, min=x): minor pair = both y's at fixed x
    __half2 a0 = __halves2half2(h00, h10);   // (y0,x0), (y1,x0)
    __half2 a1 = __halves2half2(h01, h11);   // (y0,x1), (y1,x1)
    uint2 ca;
    ca.x = *reinterpret_cast<uint32_t*>(&a0);
    ca.y = *reinterpret_cast<uint32_t*>(&a1);
    g_qA[b * QPERB + iy * QSTRIDE + ix] = ca;

    // Layout B (maj=x, min=y): minor pair = both x's at fixed y
    __half2 b0 = __halves2half2(h00, h01);   // (y0,x0), (y0,x1)
    __half2 b1 = __halves2half2(h10, h11);   // (y1,x0), (y1,x1)
    uint2 cb;
    cb.x = *reinterpret_cast<uint32_t*>(&b0);
    cb.y = *reinterpret_cast<uint32_t*>(&b1);
    g_qB[b * QPERB + ix * QSTRIDE + iy] = cb;
}

// ---------------------------------------------------------------------
__global__ void __launch_bounds__(128) fanproj_main_kernel(float* __restrict__ out)
{
    int d = blockIdx.x * blockDim.x + threadIdx.x;   // detector 0..383
    int p = blockIdx.y;                              // angle    0..255
    int b = blockIdx.z;                              // batch    0..1
    if (d >= N_DET) return;

    float theta = (float)p * TH_STEP;
    float sn, cs;
    sincosf(theta, &sn, &cs);

    float off = ((float)d - (float)(N_DET - 1) * 0.5f) * DETSP;

    // unit ray dir
    float rx = SDD_F * cs - off * sn;
    float ry = SDD_F * sn + off * cs;
    float inv = rsqrtf(SDD_F * SDD_F + off * off);
    rx *= inv;
    ry *= inv;

    // source position in (unpadded) pixel coords
    float cxp = fmaf(-SID_F, cs, 127.5f);
    float cyp = fmaf(-SID_F, sn, 127.5f);

    // --- ray/box interval: fx,fy in (-1, 256) ---
    float rxs = copysignf(fmaxf(fabsf(rx), 1e-10f), rx);
    float rys = copysignf(fmaxf(fabsf(ry), 1e-10f), ry);
    float ivx = 1.0f / rxs;
    float ivy = 1.0f / rys;
    float tx1 = (-1.0f  - cxp) * ivx;
    float tx2 = (256.0f - cxp) * ivx;
    float ty1 = (-1.0f  - cyp) * ivy;
    float ty2 = (256.0f - cyp) * ivy;
    float tlo = fmaxf(fmaxf(fminf(tx1, tx2), fminf(ty1, ty2)), T_BASE);
    float thi = fminf(fminf(fmaxf(tx1, tx2), fmaxf(ty1, ty2)), T_END);

    float slo = fmaf(tlo - T_BASE, INV_DT, -0.5f);
    float shi = fmaf(thi - T_BASE, INV_DT, -0.5f);
    int s0 = max(0,      __float2int_rd(slo) - 1);
    int s1 = min(N_SAMP, __float2int_ru(shi) + 2);

    // layout choice: minor coord = larger |u| component; u = (-sn, cs)
    bool useA = fabsf(sn) >= fabsf(cs);
    float rMin = useA ? rx : ry;
    float rMaj = useA ? ry : rx;
    float cMin = (useA ? cxp : cyp) + (float)QPAD;
    float cMaj = (useA ? cyp : cxp) + (float)QPAD;
    const uint2* __restrict__ quad = (useA ? g_qA : g_qB) + b * QPERB;

    float drMin = rMin * DT_F;
    float drMaj = rMaj * DT_F;
    float bMin  = fmaf(T_BASE, rMin, cMin);
    float bMaj  = fmaf(T_BASE, rMaj, cMaj);

    float acc = 0.f;
    float fs  = (float)s0 + 0.5f;

    #pragma unroll 4
    for (int s = s0; s < s1; ++s) {
        float fM = fmaf(fs, drMaj, bMaj);
        float fm = fmaf(fs, drMin, bMin);
        fs += 1.0f;
        int iM = __float2int_rd(fM);
        int im = __float2int_rd(fm);
        float wM = fM - (float)iM;
        float wm = fm - (float)im;

        uint2 q = __ldg(quad + iM * QSTRIDE + im);
        __half2 h0 = *reinterpret_cast<__half2*>(&q.x);
        __half2 h1 = *reinterpret_cast<__half2*>(&q.y);
        __half2 hm = __hfma2(__float2half2_rn(wm), __hsub2(h1, h0), h0);
        float2 f = __half22float2(hm);
        acc += fmaf(wM, f.y - f.x, f.x);
    }

    out[(b * N_PROJ + p) * N_DET + d] = acc * DT_F;
}

// ---------------------------------------------------------------------
extern "C" void kernel_launch(void* const* d_in, const int* in_sizes, int n_in,
                              void* d_out, int out_size)
{
    const float* x = (const float*)d_in[0];
    float* out = (float*)d_out;

    const int prep_total = 2 * QN * QN;
    fanproj_prep_kernel<<<(prep_total + 255) / 256, 256>>>(x);

    dim3 grid((N_DET + 127) / 128, N_PROJ, 2);
    fanproj_main_kernel<<<grid, 128>>>(out);
}

// round 4
// speedup vs baseline: 1.9659x; 1.3845x over previous
#include <cuda_runtime.h>
#include <cuda_fp16.h>
#include <cstdint>

// ---------------- geometry constants (match reference) ----------------
#define VOL      256
#define N_PROJ   256
#define N_DET    384
#define N_SAMP   256
#define SID_F    400.0f
#define SDD_F    800.0f
#define DETSP    1.2f

#define TH_STEP  0.024543692442321777f   // 2*pi/256 in fp32
#define DT_F     1.4142135623730951f     // diag/N = sqrt(2)
#define INV_DT   0.7071067811865476f
#define T_BASE   218.98066401624382f     // SID - diag/2
#define T_END    581.0193359837562f      // SID + diag/2

// Padded quad grid: cell i <-> corner coord c0 = i - 4, c0 in [-4, 259].
// Cells with c0 <= -2 or c0 >= 256 are all-zero, absorbing the <=2.83px
// interval-clipping slack without per-sample clamps.
#define QN       264
#define QSTRIDE  264
#define QPAD     4
#define QPERB    (QN * QSTRIDE)

// Batch-interleaved fp16 quad cells (16B): each half2 = {batch0, batch1}.
// uint4: .x = c(M0,m0), .y = c(M0,m1), .z = c(M1,m0), .w = c(M1,m1)
// Layout A: maj = y, min = x.   Layout B: maj = x, min = y.
// 2 layouts x 264x264 x 16B = ~2.23 MB static scratch.
__device__ uint4 g_qA[QPERB];
__device__ uint4 g_qB[QPERB];

// ---------------------------------------------------------------------
__global__ void fanproj_prep_kernel(const float* __restrict__ img)
{
    int idx = blockIdx.x * blockDim.x + threadIdx.x;
    const int total = QN * QN;
    if (idx >= total) return;

    int iy = idx / QN;
    int ix = idx - iy * QN;
    int y0 = iy - QPAD;
    int x0 = ix - QPAD;

    // fetch 4 corners x 2 batches (zero outside image)
    float v[2][4];  // [batch][corner: 00,01,10,11]  (01 = y0,x0+1)
    bool xa = (x0 >= 0)     && (x0 < VOL);
    bool xb = (x0 + 1 >= 0) && (x0 + 1 < VOL);
    bool ya = (y0 >= 0)     && (y0 < VOL);
    bool yb = (y0 + 1 >= 0) && (y0 + 1 < VOL);
    #pragma unroll
    for (int b = 0; b < 2; ++b) {
        const float* im = img + b * (VOL * VOL);
        v[b][0] = (ya && xa) ? im[y0 * VOL + x0]           : 0.f;
        v[b][1] = (ya && xb) ? im[y0 * VOL + x0 + 1]       : 0.f;
        v[b][2] = (yb && xa) ? im[(y0 + 1) * VOL + x0]     : 0.f;
        v[b][3] = (yb && xb) ? im[(y0 + 1) * VOL + x0 + 1] : 0.f;
    }

    __half2 h00 = __halves2half2(__float2half_rn(v[0][0]), __float2half_rn(v[1][0]));
    __half2 h01 = __halves2half2(__float2half_rn(v[0][1]), __float2half_rn(v[1][1]));
    __half2 h10 = __halves2half2(__float2half_rn(v[0][2]), __float2half_rn(v[1][2]));
    __half2 h11 = __halves2half2(__float2half_rn(v[0][3]), __float2half_rn(v[1][3]));

    // Layout A (maj=y, min=x): minor step = x
    uint4 ca;
    ca.x = *reinterpret_cast<uint32_t*>(&h00);   // (y0,x0)
    ca.y = *reinterpret_cast<uint32_t*>(&h01);   // (y0,x1)
    ca.z = *reinterpret_cast<uint32_t*>(&h10);   // (y1,x0)
    ca.w = *reinterpret_cast<uint32_t*>(&h11);   // (y1,x1)
    g_qA[iy * QSTRIDE + ix] = ca;

    // Layout B (maj=x, min=y): minor step = y
    uint4 cb;
    cb.x = *reinterpret_cast<uint32_t*>(&h00);   // (y0,x0)
    cb.y = *reinterpret_cast<uint32_t*>(&h10);   // (y1,x0)  minor+1
    cb.z = *reinterpret_cast<uint32_t*>(&h01);   // (y0,x1)  major+1
    cb.w = *reinterpret_cast<uint32_t*>(&h11);   // (y1,x1)
    g_qB[ix * QSTRIDE + iy] = cb;
}

// ---------------------------------------------------------------------
// blockDim (32,4): 32 detectors x 4 ray segments. Each thread integrates
// both batches over a quarter of the clipped sample range; block-level
// smem reduction combines segments.
// ---------------------------------------------------------------------
__global__ void __launch_bounds__(128) fanproj_main_kernel(float* __restrict__ out)
{
    int d   = blockIdx.x * 32 + threadIdx.x;         // detector 0..383
    int p   = blockIdx.y;                            // angle    0..255
    int seg = threadIdx.y;                           // segment  0..3

    float theta = (float)p * TH_STEP;
    float sn, cs;
    sincosf(theta, &sn, &cs);

    float off = ((float)d - (float)(N_DET - 1) * 0.5f) * DETSP;

    float rx = SDD_F * cs - off * sn;
    float ry = SDD_F * sn + off * cs;
    float inv = rsqrtf(SDD_F * SDD_F + off * off);
    rx *= inv;
    ry *= inv;

    float cxp = fmaf(-SID_F, cs, 127.5f);
    float cyp = fmaf(-SID_F, sn, 127.5f);

    // ray/box interval: pixel coords in (-1, 256)
    float rxs = copysignf(fmaxf(fabsf(rx), 1e-10f), rx);
    float rys = copysignf(fmaxf(fabsf(ry), 1e-10f), ry);
    float ivx = 1.0f / rxs;
    float ivy = 1.0f / rys;
    float tx1 = (-1.0f  - cxp) * ivx;
    float tx2 = (256.0f - cxp) * ivx;
    float ty1 = (-1.0f  - cyp) * ivy;
    float ty2 = (256.0f - cyp) * ivy;
    float tlo = fmaxf(fmaxf(fminf(tx1, tx2), fminf(ty1, ty2)), T_BASE);
    float thi = fminf(fminf(fmaxf(tx1, tx2), fmaxf(ty1, ty2)), T_END);

    float slo = fmaf(tlo - T_BASE, INV_DT, -0.5f);
    float shi = fmaf(thi - T_BASE, INV_DT, -0.5f);
    int s0 = max(0,      __float2int_rd(slo) - 1);
    int s1 = min(N_SAMP, __float2int_ru(shi) + 2);
    int len = max(0, s1 - s0);

    int a0 = s0 + ((len * seg) >> 2);
    int a1 = s0 + ((len * (seg + 1)) >> 2);

    // layout: minor coord = larger |u| component; u = (-sn, cs)
    bool useA = fabsf(sn) >= fabsf(cs);
    float rMin = useA ? rx : ry;
    float rMaj = useA ? ry : rx;
    float cMin = (useA ? cxp : cyp) + (float)QPAD;
    float cMaj = (useA ? cyp : cxp) + (float)QPAD;
    const uint4* __restrict__ quad = useA ? g_qA : g_qB;

    float drMin = rMin * DT_F;
    float drMaj = rMaj * DT_F;
    float bMin  = fmaf(T_BASE, rMin, cMin);
    float bMaj  = fmaf(T_BASE, rMaj, cMaj);

    float acc0 = 0.f, acc1 = 0.f;
    float fs = (float)a0 + 0.5f;

    #pragma unroll 4
    for (int s = a0; s < a1; ++s) {
        float fM = fmaf(fs, drMaj, bMaj);
        float fm = fmaf(fs, drMin, bMin);
        fs += 1.0f;
        int iM = __float2int_rd(fM);
        int im = __float2int_rd(fm);
        float wM = fM - (float)iM;
        float wm = fm - (float)im;

        uint4 q = __ldg(quad + iM * QSTRIDE + im);
        __half2 c00 = *reinterpret_cast<__half2*>(&q.x);
        __half2 c01 = *reinterpret_cast<__half2*>(&q.y);
        __half2 c10 = *reinterpret_cast<__half2*>(&q.z);
        __half2 c11 = *reinterpret_cast<__half2*>(&q.w);

        __half2 w2 = __float2half2_rn(wm);
        __half2 l0 = __hfma2(w2, __hsub2(c01, c00), c00);  // at M0, both batches
        __half2 l1 = __hfma2(w2, __hsub2(c11, c10), c10);  // at M1, both batches

        float2 f0 = __half22float2(l0);
        float2 f1 = __half22float2(l1);
        acc0 += fmaf(wM, f1.x - f0.x, f0.x);
        acc1 += fmaf(wM, f1.y - f0.y, f0.y);
    }

    // combine 4 segments
    __shared__ float2 red[128];
    red[seg * 32 + threadIdx.x] = make_float2(acc0, acc1);
    __syncthreads();
    if (seg == 0) {
        float2 r = red[threadIdx.x];
        float2 r1 = red[32 + threadIdx.x];
        float2 r2 = red[64 + threadIdx.x];
        float2 r3 = red[96 + threadIdx.x];
        float s0v = (r.x + r1.x) + (r2.x + r3.x);
        float s1v = (r.y + r1.y) + (r2.y + r3.y);
        out[p * N_DET + d]                     = s0v * DT_F;   // batch 0
        out[N_PROJ * N_DET + p * N_DET + d]    = s1v * DT_F;   // batch 1
    }
}

// ---------------------------------------------------------------------
extern "C" void kernel_launch(void* const* d_in, const int* in_sizes, int n_in,
                              void* d_out, int out_size)
{
    const float* x = (const float*)d_in[0];
    float* out = (float*)d_out;

    const int prep_total = QN * QN;
    fanproj_prep_kernel<<<(prep_total + 255) / 256, 256>>>(x);

    dim3 grid(N_DET / 32, N_PROJ);
    dim3 block(32, 4);
    fanproj_main_kernel<<<grid, block>>>(out);
}

// round 5
// speedup vs baseline: 1.9845x; 1.0095x over previous
#include <cuda_runtime.h>
#include <cuda_fp16.h>
#include <cstdint>

// ---------------- geometry constants (match reference) ----------------
#define VOL      256
#define N_PROJ   256
#define N_DET    384
#define N_SAMP   256
#define SID_F    400.0f
#define SDD_F    800.0f
#define DETSP    1.2f

#define TH_STEP  0.024543692442321777f   // 2*pi/256 in fp32
#define DT_F     1.4142135623730951f     // diag/N = sqrt(2)
#define INV_DT   0.7071067811865476f
#define T_BASE   218.98066401624382f     // SID - diag/2
#define T_END    581.0193359837562f      // SID + diag/2

#define MAGICF   12582912.0f             // 2^23 + 2^22

// Padded quad grid: cell i <-> corner coord c0 = i - 4, c0 in [-4, 259].
// Cells with c0 <= -2 or c0 >= 256 are all-zero, absorbing the <=2.83px
// interval-clipping slack without per-sample clamps.
#define QN       264
#define QSTRIDE  264
#define QPAD     4
#define QPERB    (QN * QSTRIDE)

// Batch-interleaved, basis-transformed fp16 cells (16B):
//   .x = half2{a  b0,b1}   a = mean of 4 corners
//   .y = half2{b  b0,b1}   b = minor-coef   (w' in (-0.5,0.5])
//   .z = half2{c  b0,b1}   c = major-coef
//   .w = half2{e  b0,b1}   e = cross-coef
// v = (a + b*w'm) + W'M*(c + e*w'm)
// Layout A: maj = y, min = x.   Layout B: maj = x, min = y.
__device__ uint4 g_qA[QPERB];
__device__ uint4 g_qB[QPERB];

// ---------------------------------------------------------------------
__global__ void fanproj_prep_kernel(const float* __restrict__ img)
{
    int idx = blockIdx.x * blockDim.x + threadIdx.x;
    const int total = QN * QN;
    if (idx >= total) return;

    int iy = idx / QN;
    int ix = idx - iy * QN;
    int y0 = iy - QPAD;
    int x0 = ix - QPAD;

    float a[2], bx[2], cy[2], e[2];
    bool xa = (x0 >= 0)     && (x0 < VOL);
    bool xb = (x0 + 1 >= 0) && (x0 + 1 < VOL);
    bool ya = (y0 >= 0)     && (y0 < VOL);
    bool yb = (y0 + 1 >= 0) && (y0 + 1 < VOL);
    #pragma unroll
    for (int b = 0; b < 2; ++b) {
        const float* im = img + b * (VOL * VOL);
        float v00 = (ya && xa) ? im[y0 * VOL + x0]           : 0.f;
        float v01 = (ya && xb) ? im[y0 * VOL + x0 + 1]       : 0.f;
        float v10 = (yb && xa) ? im[(y0 + 1) * VOL + x0]     : 0.f;
        float v11 = (yb && xb) ? im[(y0 + 1) * VOL + x0 + 1] : 0.f;
        a[b]  = 0.25f * ((v00 + v01) + (v10 + v11));
        bx[b] = 0.5f  * ((v01 - v00) + (v11 - v10));   // x-coef
        cy[b] = 0.5f  * ((v10 - v00) + (v11 - v01));   // y-coef
        e[b]  = (v11 - v10) - (v01 - v00);             // cross
    }

    __half2 hA = __halves2half2(__float2half_rn(a[0]),  __float2half_rn(a[1]));
    __half2 hB = __halves2half2(__float2half_rn(bx[0]), __float2half_rn(bx[1]));
    __half2 hC = __halves2half2(__float2half_rn(cy[0]), __float2half_rn(cy[1]));
    __half2 hE = __halves2half2(__float2half_rn(e[0]),  __float2half_rn(e[1]));

    uint4 ca;   // layout A: minor = x -> b = x-coef, c = y-coef
    ca.x = *reinterpret_cast<uint32_t*>(&hA);
    ca.y = *reinterpret_cast<uint32_t*>(&hB);
    ca.z = *reinterpret_cast<uint32_t*>(&hC);
    ca.w = *reinterpret_cast<uint32_t*>(&hE);
    g_qA[iy * QSTRIDE + ix] = ca;

    uint4 cb;   // layout B: minor = y -> b = y-coef, c = x-coef
    cb.x = *reinterpret_cast<uint32_t*>(&hA);
    cb.y = *reinterpret_cast<uint32_t*>(&hC);
    cb.z = *reinterpret_cast<uint32_t*>(&hB);
    cb.w = *reinterpret_cast<uint32_t*>(&hE);
    g_qB[ix * QSTRIDE + iy] = cb;
}

// ---------------------------------------------------------------------
// blockDim (32,4): 32 detectors x 4 ray segments; both batches per thread.
// ---------------------------------------------------------------------
__global__ void __launch_bounds__(128) fanproj_main_kernel(float* __restrict__ out)
{
    int d   = blockIdx.x * 32 + threadIdx.x;         // detector 0..383
    int p   = blockIdx.y;                            // angle    0..255
    int seg = threadIdx.y;                           // segment  0..3

    float theta = (float)p * TH_STEP;
    float sn, cs;
    sincosf(theta, &sn, &cs);

    float off = ((float)d - (float)(N_DET - 1) * 0.5f) * DETSP;

    float rx = SDD_F * cs - off * sn;
    float ry = SDD_F * sn + off * cs;
    float inv = rsqrtf(SDD_F * SDD_F + off * off);
    rx *= inv;
    ry *= inv;

    float cxp = fmaf(-SID_F, cs, 127.5f);
    float cyp = fmaf(-SID_F, sn, 127.5f);

    // ray/box interval: pixel coords in (-1, 256)
    float rxs = copysignf(fmaxf(fabsf(rx), 1e-10f), rx);
    float rys = copysignf(fmaxf(fabsf(ry), 1e-10f), ry);
    float ivx = 1.0f / rxs;
    float ivy = 1.0f / rys;
    float tx1 = (-1.0f  - cxp) * ivx;
    float tx2 = (256.0f - cxp) * ivx;
    float ty1 = (-1.0f  - cyp) * ivy;
    float ty2 = (256.0f - cyp) * ivy;
    float tlo = fmaxf(fmaxf(fminf(tx1, tx2), fminf(ty1, ty2)), T_BASE);
    float thi = fminf(fminf(fmaxf(tx1, tx2), fmaxf(ty1, ty2)), T_END);

    float slo = fmaf(tlo - T_BASE, INV_DT, -0.5f);
    float shi = fmaf(thi - T_BASE, INV_DT, -0.5f);
    int s0 = max(0,      __float2int_rd(slo) - 1);
    int s1 = min(N_SAMP, __float2int_ru(shi) + 2);
    int len = max(0, s1 - s0);

    int a0 = s0 + ((len * seg) >> 2);
    int a1 = s0 + ((len * (seg + 1)) >> 2);

    // layout: minor coord = larger |u| component; u = (-sn, cs)
    bool useA = fabsf(sn) >= fabsf(cs);
    float rMin = useA ? rx : ry;
    float rMaj = useA ? ry : rx;
    float cMin = (useA ? cxp : cyp) + (float)QPAD;
    float cMaj = (useA ? cyp : cxp) + (float)QPAD;
    const uint4* __restrict__ quad = useA ? g_qA : g_qB;

    float drMin = rMin * DT_F;
    float drMaj = rMaj * DT_F;
    // -0.5 shift folded into base: magic round-to-nearest of (f - 0.5) == floor(f)
    float bMin  = fmaf(T_BASE, rMin, cMin) - 0.5f;
    float bMaj  = fmaf(T_BASE, rMaj, cMaj) - 0.5f;

    float acc0 = 0.f, acc1 = 0.f;
    float fs = (float)a0 + 0.5f;

    #pragma unroll 4
    for (int s = a0; s < a1; ++s) {
        float fM = fmaf(fs, drMaj, bMaj);     // f - 0.5 (shifted)
        float fm = fmaf(fs, drMin, bMin);
        fs += 1.0f;
        float kM = fM + MAGICF;
        float km = fm + MAGICF;
        int iM = (int)(__float_as_uint(kM) & 0x1FFu);   // = rn(f-0.5) = floor(f)
        int im = (int)(__float_as_uint(km) & 0x1FFu);
        float wM = fM - (kM - MAGICF);        // w' in (-0.5, 0.5]
        float wm = fm - (km - MAGICF);

        uint4 q = __ldg(quad + iM * QSTRIDE + im);
        __half2 A  = *reinterpret_cast<__half2*>(&q.x);
        __half2 Bc = *reinterpret_cast<__half2*>(&q.y);
        __half2 Cc = *reinterpret_cast<__half2*>(&q.z);
        __half2 Ec = *reinterpret_cast<__half2*>(&q.w);

        __half2 w2 = __float2half2_rn(wm);
        __half2 t0 = __hfma2(w2, Bc, A);      // a + b*w'm   (both batches)
        __half2 t1 = __hfma2(w2, Ec, Cc);     // c + e*w'm

        acc0 = fmaf(wM, __low2float(t1),  acc0 + __low2float(t0));
        acc1 = fmaf(wM, __high2float(t1), acc1 + __high2float(t0));
    }

    // combine 4 segments
    __shared__ float2 red[128];
    red[seg * 32 + threadIdx.x] = make_float2(acc0, acc1);
    __syncthreads();
    if (seg == 0) {
        float2 r0 = red[threadIdx.x];
        float2 r1 = red[32 + threadIdx.x];
        float2 r2 = red[64 + threadIdx.x];
        float2 r3 = red[96 + threadIdx.x];
        float v0 = (r0.x + r1.x) + (r2.x + r3.x);
        float v1 = (r0.y + r1.y) + (r2.y + r3.y);
        out[p * N_DET + d]                  = v0 * DT_F;   // batch 0
        out[N_PROJ * N_DET + p * N_DET + d] = v1 * DT_F;   // batch 1
    }
}

// ---------------------------------------------------------------------
extern "C" void kernel_launch(void* const* d_in, const int* in_sizes, int n_in,
                              void* d_out, int out_size)
{
    const float* x = (const float*)d_in[0];
    float* out = (float*)d_out;

    const int prep_total = QN * QN;
    fanproj_prep_kernel<<<(prep_total + 255) / 256, 256>>>(x);

    dim3 grid(N_DET / 32, N_PROJ);
    dim3 block(32, 4);
    fanproj_main_kernel<<<grid, block>>>(out);
}